// round 12
// baseline (speedup 1.0000x reference)
#include <cuda_runtime.h>
#include <cuda_bf16.h>

// 3-layer LSTM, B=1024, T=1024, H=20, IN=1, OUT=2, FC on last h2.
// R12: R11 (layer pipeline + gate-row split, register weights) with the batch
// loop DE-SERIALIZED: per-gb scratch buffers + two-phase step
// (phase A: all-gb MACs; one __syncwarp; phase B: all-gb cell updates).
// 1 syncwarp + 1 syncthreads per step instead of 8 syncs.

#define T_LEN 1024
#define HID   20
#define FULLM 0xffffffffu
#define NW    6

typedef unsigned long long u64;

__device__ __forceinline__ void ffma2(u64 &acc, u64 a, u64 b) {
    asm("fma.rn.f32x2 %0, %1, %2, %0;" : "+l"(acc) : "l"(a), "l"(b));
}
__device__ __forceinline__ float hadd(u64 v) {
    float lo, hi;
    asm("mov.b64 {%0, %1}, %2;" : "=f"(lo), "=f"(hi) : "l"(v));
    return lo + hi;
}

// ---- accurate fast activations (MUFU EX2/RCP, ~1e-6 err) ----
__device__ __forceinline__ float fsig(float x) {
    float e = __expf(-x);
    return __fdividef(1.0f, 1.0f + e);
}
__device__ __forceinline__ float ftanh(float x) {
    float ax = fabsf(x);
    float e  = __expf(-2.0f * ax);
    float r  = __fdividef(1.0f - e, 1.0f + e);
    return copysignf(r, x);
}
__device__ __forceinline__ float cellup(float pi, float pf, float pg, float po,
                                        float &c) {
    c = fsig(pf) * c + fsig(pi) * ftanh(pg);
    return fsig(po) * ftanh(c);
}

// 3-row MAC over 5 h-kquads (10 k-pairs) starting at weight offset `off`
__device__ __forceinline__ void mac3(u64 &aA, u64 &aB, u64 &aC,
                                     const ulonglong2* __restrict__ h,
                                     const u64* __restrict__ WA,
                                     const u64* __restrict__ WB,
                                     const u64* __restrict__ WC, int off)
{
#pragma unroll
    for (int i = 0; i < 5; i++) {
        ulonglong2 v = h[i];
        ffma2(aA, v.x, WA[off + 2*i]); ffma2(aA, v.y, WA[off + 2*i + 1]);
        ffma2(aB, v.x, WB[off + 2*i]); ffma2(aB, v.y, WB[off + 2*i + 1]);
        ffma2(aC, v.x, WC[off + 2*i]); ffma2(aC, v.y, WC[off + 2*i + 1]);
    }
}

__global__ void __launch_bounds__(NW * 32, 1)
lstm3_rows(const float* __restrict__ x,
           const float* __restrict__ wih0, const float* __restrict__ whh0,
           const float* __restrict__ bih0, const float* __restrict__ bhh0,
           const float* __restrict__ wih1, const float* __restrict__ whh1,
           const float* __restrict__ bih1, const float* __restrict__ bhh1,
           const float* __restrict__ wih2, const float* __restrict__ whh2,
           const float* __restrict__ bih2, const float* __restrict__ bhh2,
           const float* __restrict__ fcw,  const float* __restrict__ fcb,
           float* __restrict__ out)
{
    // h buffers: [layer][pipe][parity][gb][20 floats]
    __shared__ __align__(16) float4 s_h[3][2][2][4][5];
    // per-warp, PER-GB row-sum scratch, unit-major: ps[gb][u*4+g]
    __shared__ __align__(16) float s_ps[NW][4][80];

    const int tid  = threadIdx.x;
    const int lane = tid & 31;
    const int wid  = tid >> 5;

    {   // zero h buffers
        float4* p = &s_h[0][0][0][0][0];
        for (int i = tid; i < 3 * 2 * 2 * 4 * 5; i += NW * 32)
            p[i] = make_float4(0.f, 0.f, 0.f, 0.f);
    }
    __syncthreads();

    // role map: S0={L1p0,L0p0} S1={L2p0,L0p1} S2={L1p1} S3={L2p1}
    int role, pipe;
    if (wid < 4) { role = 1 + (wid & 1); pipe = wid >> 1; }
    else         { role = 0;             pipe = wid - 4;  }

    const int GBn   = (pipe == 0) ? 4 : 3;          // 7 batches per block
    const int bbase = blockIdx.x * 7 + pipe * 4;

    // gate-row assignment for this lane (rows: i 0-19, f 20-39, g 40-59, o 60-79)
    const int rA = lane;                 // rows 0..31
    const int rB = lane + 32;            // rows 32..63
    const int rC = 64 + (lane & 15);     // rows 64..79 (lanes 16..31 shadow)
    const int jc = (lane < HID) ? lane : (HID - 1);

    const int adA = (rA % 20) * 4 + rA / 20;
    const int adB = (rB % 20) * 4 + rB / 20;
    const int adC = (rC % 20) * 4 + rC / 20;

    // ---- per-lane register weights ----
    u64 WA[20], WB[20], WC[20];
    float4 Bini, wx4 = make_float4(0.f, 0.f, 0.f, 0.f);
    {
        const float* wi = (role == 0) ? wih0 : ((role == 1) ? wih1 : wih2);
        const float* wh = (role == 0) ? whh0 : ((role == 1) ? whh1 : whh2);
        const float* bi = (role == 0) ? bih0 : ((role == 1) ? bih1 : bih2);
        const float* bh = (role == 0) ? bhh0 : ((role == 1) ? bhh1 : bhh2);
        if (role == 0) {
#pragma unroll
            for (int m = 0; m < 10; m++) {
                WA[m] = *(const u64*)(wh + rA * HID + 2 * m);
                WB[m] = *(const u64*)(wh + rB * HID + 2 * m);
                WC[m] = *(const u64*)(wh + rC * HID + 2 * m);
            }
            wx4 = make_float4(wi[jc], wi[20 + jc], wi[40 + jc], wi[60 + jc]);
        } else {
#pragma unroll
            for (int m = 0; m < 10; m++) {
                WA[m]      = *(const u64*)(wi + rA * HID + 2 * m);
                WA[10 + m] = *(const u64*)(wh + rA * HID + 2 * m);
                WB[m]      = *(const u64*)(wi + rB * HID + 2 * m);
                WB[10 + m] = *(const u64*)(wh + rB * HID + 2 * m);
                WC[m]      = *(const u64*)(wi + rC * HID + 2 * m);
                WC[10 + m] = *(const u64*)(wh + rC * HID + 2 * m);
            }
        }
        Bini = make_float4(bi[jc]      + bh[jc],      bi[20 + jc] + bh[20 + jc],
                           bi[40 + jc] + bh[40 + jc], bi[60 + jc] + bh[60 + jc]);
    }

    float cst[4] = {0.f, 0.f, 0.f, 0.f};
    float xs[4]  = {0.f, 0.f, 0.f, 0.f};
    float xv[4];

    // pipeline: step n -> L0 computes t=n, L1 t=n-1, L2 t=n-2
    for (int n = 0; n <= T_LEN + 1; n++) {
        if (role == 0) {
            if (n < T_LEN) {
                if ((n & 31) == 0) {
#pragma unroll
                    for (int gb = 0; gb < 4; gb++) {
                        if (gb < GBn) {
                            int bc = bbase + gb; if (bc > 1023) bc = 1023;
                            xs[gb] = x[(long)bc * T_LEN + n + lane];
                        }
                    }
                }
                const int pw = n & 1, pr = pw ^ 1;
                // ---- phase A: all-gb MACs ----
#pragma unroll
                for (int gb = 0; gb < 4; gb++) {
                    if (gb < GBn) {
                        xv[gb] = __shfl_sync(FULLM, xs[gb], n & 31);
                        u64 aA = 0, aB = 0, aC = 0;
                        mac3(aA, aB, aC,
                             (const ulonglong2*)&s_h[0][pipe][pr][gb][0],
                             WA, WB, WC, 0);
                        s_ps[wid][gb][adA] = hadd(aA);
                        s_ps[wid][gb][adB] = hadd(aB);
                        if (lane < 16) s_ps[wid][gb][adC] = hadd(aC);
                    }
                }
                __syncwarp();
                // ---- phase B: all-gb cell updates ----
#pragma unroll
                for (int gb = 0; gb < 4; gb++) {
                    if (gb < GBn) {
                        float4 G = *(const float4*)&s_ps[wid][gb][jc * 4];
                        float gi = fmaf(xv[gb], wx4.x, G.x + Bini.x);
                        float gf = fmaf(xv[gb], wx4.y, G.y + Bini.y);
                        float gg = fmaf(xv[gb], wx4.z, G.z + Bini.z);
                        float go = fmaf(xv[gb], wx4.w, G.w + Bini.w);
                        float hn = cellup(gi, gf, gg, go, cst[gb]);
                        if (lane < HID)
                            ((float*)&s_h[0][pipe][pw][gb][0])[lane] = hn;
                    }
                }
            }
        } else if (role == 1) {
            if (n >= 1 && n <= T_LEN) {
                const int t = n - 1, pw = t & 1, pr = pw ^ 1;
#pragma unroll
                for (int gb = 0; gb < 4; gb++) {
                    if (gb < GBn) {
                        u64 aA = 0, aB = 0, aC = 0;
                        mac3(aA, aB, aC,
                             (const ulonglong2*)&s_h[0][pipe][pw][gb][0],
                             WA, WB, WC, 0);                       // h0[t]
                        mac3(aA, aB, aC,
                             (const ulonglong2*)&s_h[1][pipe][pr][gb][0],
                             WA, WB, WC, 10);                      // h1[t-1]
                        s_ps[wid][gb][adA] = hadd(aA);
                        s_ps[wid][gb][adB] = hadd(aB);
                        if (lane < 16) s_ps[wid][gb][adC] = hadd(aC);
                    }
                }
                __syncwarp();
#pragma unroll
                for (int gb = 0; gb < 4; gb++) {
                    if (gb < GBn) {
                        float4 G = *(const float4*)&s_ps[wid][gb][jc * 4];
                        float hn = cellup(G.x + Bini.x, G.y + Bini.y,
                                          G.z + Bini.z, G.w + Bini.w, cst[gb]);
                        if (lane < HID)
                            ((float*)&s_h[1][pipe][pw][gb][0])[lane] = hn;
                    }
                }
            }
        } else {
            if (n >= 2) {
                const int t = n - 2, pw = t & 1, pr = pw ^ 1;
#pragma unroll
                for (int gb = 0; gb < 4; gb++) {
                    if (gb < GBn) {
                        u64 aA = 0, aB = 0, aC = 0;
                        mac3(aA, aB, aC,
                             (const ulonglong2*)&s_h[1][pipe][pw][gb][0],
                             WA, WB, WC, 0);                       // h1[t]
                        mac3(aA, aB, aC,
                             (const ulonglong2*)&s_h[2][pipe][pr][gb][0],
                             WA, WB, WC, 10);                      // h2[t-1]
                        s_ps[wid][gb][adA] = hadd(aA);
                        s_ps[wid][gb][adB] = hadd(aB);
                        if (lane < 16) s_ps[wid][gb][adC] = hadd(aC);
                    }
                }
                __syncwarp();
#pragma unroll
                for (int gb = 0; gb < 4; gb++) {
                    if (gb < GBn) {
                        float4 G = *(const float4*)&s_ps[wid][gb][jc * 4];
                        float hn = cellup(G.x + Bini.x, G.y + Bini.y,
                                          G.z + Bini.z, G.w + Bini.w, cst[gb]);
                        if (lane < HID)
                            ((float*)&s_h[2][pipe][pw][gb][0])[lane] = hn;
                    }
                }
            }
        }
        // block barrier: publishes h across roles AND fences scratch reuse
        __syncthreads();
    }

    // ---- final FC on h2[T-1] by the L2 warps ----
    if (role == 2) {
        const int pfin = (T_LEN - 1) & 1;
#pragma unroll
        for (int gb = 0; gb < 4; gb++) {
            if (gb < GBn) {
                const int b = bbase + gb;
                float hv = ((const float*)&s_h[2][pipe][pfin][gb][0])[jc];
                float p0 = (lane < HID) ? hv * fcw[jc]       : 0.f;
                float p1 = (lane < HID) ? hv * fcw[HID + jc] : 0.f;
#pragma unroll
                for (int off = 16; off > 0; off >>= 1) {
                    p0 += __shfl_xor_sync(FULLM, p0, off);
                    p1 += __shfl_xor_sync(FULLM, p1, off);
                }
                if (lane == 0 && b < 1024) {
                    out[b * 2 + 0] = p0 + fcb[0];
                    out[b * 2 + 1] = p1 + fcb[1];
                }
            }
        }
    }
}

extern "C" void kernel_launch(void* const* d_in, const int* in_sizes, int n_in,
                              void* d_out, int out_size) {
    const float* x    = (const float*)d_in[0];
    const float* wih0 = (const float*)d_in[1];
    const float* whh0 = (const float*)d_in[2];
    const float* bih0 = (const float*)d_in[3];
    const float* bhh0 = (const float*)d_in[4];
    const float* wih1 = (const float*)d_in[5];
    const float* whh1 = (const float*)d_in[6];
    const float* bih1 = (const float*)d_in[7];
    const float* bhh1 = (const float*)d_in[8];
    const float* wih2 = (const float*)d_in[9];
    const float* whh2 = (const float*)d_in[10];
    const float* bih2 = (const float*)d_in[11];
    const float* bhh2 = (const float*)d_in[12];
    const float* fcw  = (const float*)d_in[13];
    const float* fcb  = (const float*)d_in[14];
    float* out = (float*)d_out;

    // 147 blocks x 7 batches (pipes of 4 and 3): 1029 slots for 1024 batches
    lstm3_rows<<<147, NW * 32>>>(x, wih0, whh0, bih0, bhh0,
                                 wih1, whh1, bih1, bhh1,
                                 wih2, whh2, bih2, bhh2,
                                 fcw, fcb, out);
}

// round 13
// speedup vs baseline: 1.3085x; 1.3085x over previous
#include <cuda_runtime.h>
#include <cuda_bf16.h>

// 3-layer LSTM, B=1024, T=1024, H=20, IN=1, OUT=2, FC on last h2.
// R13: R11 structure (layer pipeline, gate-row split over 32 lanes, register
// weights) with blocks shrunk to 2 pipes x GB=2 (4 batches/block, 192 thr)
// and __launch_bounds__(192, 2) so TWO independent blocks co-reside per SM.
// Two independent __syncthreads domains per SM break the per-step convoy:
// while one block waits at its barrier, the other block's warps issue.

#define T_LEN 1024
#define HID   20
#define FULLM 0xffffffffu
#define NW    6
#define GB    2

typedef unsigned long long u64;

__device__ __forceinline__ void ffma2(u64 &acc, u64 a, u64 b) {
    asm("fma.rn.f32x2 %0, %1, %2, %0;" : "+l"(acc) : "l"(a), "l"(b));
}
__device__ __forceinline__ float hadd(u64 v) {
    float lo, hi;
    asm("mov.b64 {%0, %1}, %2;" : "=f"(lo), "=f"(hi) : "l"(v));
    return lo + hi;
}

// ---- accurate fast activations (MUFU EX2/RCP, ~1e-6 err) ----
__device__ __forceinline__ float fsig(float x) {
    float e = __expf(-x);
    return __fdividef(1.0f, 1.0f + e);
}
__device__ __forceinline__ float ftanh(float x) {
    float ax = fabsf(x);
    float e  = __expf(-2.0f * ax);
    float r  = __fdividef(1.0f - e, 1.0f + e);
    return copysignf(r, x);
}
__device__ __forceinline__ float cellup(float pi, float pf, float pg, float po,
                                        float &c) {
    c = fsig(pf) * c + fsig(pi) * ftanh(pg);
    return fsig(po) * ftanh(c);
}

// 3-row MAC over 5 h-kquads (10 k-pairs) starting at weight offset `off`
__device__ __forceinline__ void mac3(u64 &aA, u64 &aB, u64 &aC,
                                     const ulonglong2* __restrict__ h,
                                     const u64* __restrict__ WA,
                                     const u64* __restrict__ WB,
                                     const u64* __restrict__ WC, int off)
{
#pragma unroll
    for (int i = 0; i < 5; i++) {
        ulonglong2 v = h[i];
        ffma2(aA, v.x, WA[off + 2*i]); ffma2(aA, v.y, WA[off + 2*i + 1]);
        ffma2(aB, v.x, WB[off + 2*i]); ffma2(aB, v.y, WB[off + 2*i + 1]);
        ffma2(aC, v.x, WC[off + 2*i]); ffma2(aC, v.y, WC[off + 2*i + 1]);
    }
}

__global__ void __launch_bounds__(NW * 32, 2)
lstm3_rows(const float* __restrict__ x,
           const float* __restrict__ wih0, const float* __restrict__ whh0,
           const float* __restrict__ bih0, const float* __restrict__ bhh0,
           const float* __restrict__ wih1, const float* __restrict__ whh1,
           const float* __restrict__ bih1, const float* __restrict__ bhh1,
           const float* __restrict__ wih2, const float* __restrict__ whh2,
           const float* __restrict__ bih2, const float* __restrict__ bhh2,
           const float* __restrict__ fcw,  const float* __restrict__ fcb,
           float* __restrict__ out)
{
    // h buffers: [layer][pipe][parity][gb][20 floats]
    __shared__ __align__(16) float4 s_h[3][2][2][GB][5];
    // per-warp, per-gb row-sum scratch, unit-major: ps[gb][u*4+g]
    __shared__ __align__(16) float s_ps[NW][GB][80];

    const int tid  = threadIdx.x;
    const int lane = tid & 31;
    const int wid  = tid >> 5;

    {   // zero h buffers
        float4* p = &s_h[0][0][0][0][0];
        for (int i = tid; i < 3 * 2 * 2 * GB * 5; i += NW * 32)
            p[i] = make_float4(0.f, 0.f, 0.f, 0.f);
    }
    __syncthreads();

    // role map: S0={L1p0,L0p0} S1={L2p0,L0p1} S2={L1p1} S3={L2p1}
    int role, pipe;
    if (wid < 4) { role = 1 + (wid & 1); pipe = wid >> 1; }
    else         { role = 0;             pipe = wid - 4;  }

    const int bbase = blockIdx.x * (2 * GB) + pipe * GB;

    // gate-row assignment (rows: i 0-19, f 20-39, g 40-59, o 60-79)
    const int rA = lane;                 // rows 0..31
    const int rB = lane + 32;            // rows 32..63
    const int rC = 64 + (lane & 15);     // rows 64..79 (lanes 16..31 shadow)
    const int jc = (lane < HID) ? lane : (HID - 1);

    const int adA = (rA % 20) * 4 + rA / 20;
    const int adB = (rB % 20) * 4 + rB / 20;
    const int adC = (rC % 20) * 4 + rC / 20;

    // ---- per-lane register weights ----
    u64 WA[20], WB[20], WC[20];
    float4 Bini, wx4 = make_float4(0.f, 0.f, 0.f, 0.f);
    {
        const float* wi = (role == 0) ? wih0 : ((role == 1) ? wih1 : wih2);
        const float* wh = (role == 0) ? whh0 : ((role == 1) ? whh1 : whh2);
        const float* bi = (role == 0) ? bih0 : ((role == 1) ? bih1 : bih2);
        const float* bh = (role == 0) ? bhh0 : ((role == 1) ? bhh1 : bhh2);
        if (role == 0) {
#pragma unroll
            for (int m = 0; m < 10; m++) {
                WA[m] = *(const u64*)(wh + rA * HID + 2 * m);
                WB[m] = *(const u64*)(wh + rB * HID + 2 * m);
                WC[m] = *(const u64*)(wh + rC * HID + 2 * m);
            }
            wx4 = make_float4(wi[jc], wi[20 + jc], wi[40 + jc], wi[60 + jc]);
        } else {
#pragma unroll
            for (int m = 0; m < 10; m++) {
                WA[m]      = *(const u64*)(wi + rA * HID + 2 * m);
                WA[10 + m] = *(const u64*)(wh + rA * HID + 2 * m);
                WB[m]      = *(const u64*)(wi + rB * HID + 2 * m);
                WB[10 + m] = *(const u64*)(wh + rB * HID + 2 * m);
                WC[m]      = *(const u64*)(wi + rC * HID + 2 * m);
                WC[10 + m] = *(const u64*)(wh + rC * HID + 2 * m);
            }
        }
        Bini = make_float4(bi[jc]      + bh[jc],      bi[20 + jc] + bh[20 + jc],
                           bi[40 + jc] + bh[40 + jc], bi[60 + jc] + bh[60 + jc]);
    }

    float cst[GB] = {0.f, 0.f};
    float xs[GB]  = {0.f, 0.f};

    // pipeline: step n -> L0 computes t=n, L1 t=n-1, L2 t=n-2
    for (int n = 0; n <= T_LEN + 1; n++) {
        if (role == 0) {
            if (n < T_LEN) {
                if ((n & 31) == 0) {
#pragma unroll
                    for (int gb = 0; gb < GB; gb++)
                        xs[gb] = x[(long)(bbase + gb) * T_LEN + n + lane];
                }
                const int pw = n & 1, pr = pw ^ 1;
#pragma unroll
                for (int gb = 0; gb < GB; gb++) {
                    float xv = __shfl_sync(FULLM, xs[gb], n & 31);
                    u64 aA = 0, aB = 0, aC = 0;
                    mac3(aA, aB, aC,
                         (const ulonglong2*)&s_h[0][pipe][pr][gb][0],
                         WA, WB, WC, 0);
                    s_ps[wid][gb][adA] = hadd(aA);
                    s_ps[wid][gb][adB] = hadd(aB);
                    if (lane < 16) s_ps[wid][gb][adC] = hadd(aC);
                    __syncwarp();
                    float4 G = *(const float4*)&s_ps[wid][gb][jc * 4];
                    float gi = fmaf(xv, wx4.x, G.x + Bini.x);
                    float gf = fmaf(xv, wx4.y, G.y + Bini.y);
                    float gg = fmaf(xv, wx4.z, G.z + Bini.z);
                    float go = fmaf(xv, wx4.w, G.w + Bini.w);
                    float hn = cellup(gi, gf, gg, go, cst[gb]);
                    if (lane < HID)
                        ((float*)&s_h[0][pipe][pw][gb][0])[lane] = hn;
                    __syncwarp();
                }
            }
        } else if (role == 1) {
            if (n >= 1 && n <= T_LEN) {
                const int t = n - 1, pw = t & 1, pr = pw ^ 1;
#pragma unroll
                for (int gb = 0; gb < GB; gb++) {
                    u64 aA = 0, aB = 0, aC = 0;
                    mac3(aA, aB, aC,
                         (const ulonglong2*)&s_h[0][pipe][pw][gb][0],
                         WA, WB, WC, 0);                       // h0[t]
                    mac3(aA, aB, aC,
                         (const ulonglong2*)&s_h[1][pipe][pr][gb][0],
                         WA, WB, WC, 10);                      // h1[t-1]
                    s_ps[wid][gb][adA] = hadd(aA);
                    s_ps[wid][gb][adB] = hadd(aB);
                    if (lane < 16) s_ps[wid][gb][adC] = hadd(aC);
                    __syncwarp();
                    float4 G = *(const float4*)&s_ps[wid][gb][jc * 4];
                    float hn = cellup(G.x + Bini.x, G.y + Bini.y,
                                      G.z + Bini.z, G.w + Bini.w, cst[gb]);
                    if (lane < HID)
                        ((float*)&s_h[1][pipe][pw][gb][0])[lane] = hn;
                    __syncwarp();
                }
            }
        } else {
            if (n >= 2) {
                const int t = n - 2, pw = t & 1, pr = pw ^ 1;
#pragma unroll
                for (int gb = 0; gb < GB; gb++) {
                    u64 aA = 0, aB = 0, aC = 0;
                    mac3(aA, aB, aC,
                         (const ulonglong2*)&s_h[1][pipe][pw][gb][0],
                         WA, WB, WC, 0);                       // h1[t]
                    mac3(aA, aB, aC,
                         (const ulonglong2*)&s_h[2][pipe][pr][gb][0],
                         WA, WB, WC, 10);                      // h2[t-1]
                    s_ps[wid][gb][adA] = hadd(aA);
                    s_ps[wid][gb][adB] = hadd(aB);
                    if (lane < 16) s_ps[wid][gb][adC] = hadd(aC);
                    __syncwarp();
                    float4 G = *(const float4*)&s_ps[wid][gb][jc * 4];
                    float hn = cellup(G.x + Bini.x, G.y + Bini.y,
                                      G.z + Bini.z, G.w + Bini.w, cst[gb]);
                    if (lane < HID)
                        ((float*)&s_h[2][pipe][pw][gb][0])[lane] = hn;
                    __syncwarp();
                }
            }
        }
        __syncthreads();
    }

    // ---- final FC on h2[T-1] by the L2 warps ----
    if (role == 2) {
        const int pfin = (T_LEN - 1) & 1;
#pragma unroll
        for (int gb = 0; gb < GB; gb++) {
            const int b = bbase + gb;
            float hv = ((const float*)&s_h[2][pipe][pfin][gb][0])[jc];
            float p0 = (lane < HID) ? hv * fcw[jc]       : 0.f;
            float p1 = (lane < HID) ? hv * fcw[HID + jc] : 0.f;
#pragma unroll
            for (int off = 16; off > 0; off >>= 1) {
                p0 += __shfl_xor_sync(FULLM, p0, off);
                p1 += __shfl_xor_sync(FULLM, p1, off);
            }
            if (lane == 0) {
                out[b * 2 + 0] = p0 + fcb[0];
                out[b * 2 + 1] = p1 + fcb[1];
            }
        }
    }
}

extern "C" void kernel_launch(void* const* d_in, const int* in_sizes, int n_in,
                              void* d_out, int out_size) {
    const float* x    = (const float*)d_in[0];
    const float* wih0 = (const float*)d_in[1];
    const float* whh0 = (const float*)d_in[2];
    const float* bih0 = (const float*)d_in[3];
    const float* bhh0 = (const float*)d_in[4];
    const float* wih1 = (const float*)d_in[5];
    const float* whh1 = (const float*)d_in[6];
    const float* bih1 = (const float*)d_in[7];
    const float* bhh1 = (const float*)d_in[8];
    const float* wih2 = (const float*)d_in[9];
    const float* whh2 = (const float*)d_in[10];
    const float* bih2 = (const float*)d_in[11];
    const float* bhh2 = (const float*)d_in[12];
    const float* fcw  = (const float*)d_in[13];
    const float* fcb  = (const float*)d_in[14];
    float* out = (float*)d_out;

    // 256 blocks x 4 batches (2 pipes x GB=2); 2 blocks co-resident per SM
    lstm3_rows<<<256, NW * 32>>>(x, wih0, whh0, bih0, bhh0,
                                 wih1, whh1, bih1, bhh1,
                                 wih2, whh2, bih2, bhh2,
                                 fcw, fcb, out);
}

// round 14
// speedup vs baseline: 1.6482x; 1.2596x over previous
#include <cuda_runtime.h>
#include <cuda_bf16.h>

// 3-layer LSTM, B=1024, T=1024, H=20, IN=1, OUT=2, FC on last h2.
// R14 = R13 (layer pipeline, gate-row split, register weights, 2 blocks/SM)
//  + tanh.approx.f32 activations (1 MUFU vs EX2/RCP chains)
//  + per-pipe named barriers (bar.sync 1+pipe, 96): 4 sync domains per SM.

#define T_LEN 1024
#define HID   20
#define FULLM 0xffffffffu
#define NW    6
#define GB    2

typedef unsigned long long u64;

__device__ __forceinline__ void ffma2(u64 &acc, u64 a, u64 b) {
    asm("fma.rn.f32x2 %0, %1, %2, %0;" : "+l"(acc) : "l"(a), "l"(b));
}
__device__ __forceinline__ float hadd(u64 v) {
    float lo, hi;
    asm("mov.b64 {%0, %1}, %2;" : "=f"(lo), "=f"(hi) : "l"(v));
    return lo + hi;
}

// ---- MUFU.TANH-based activations (single-instruction approx) ----
__device__ __forceinline__ float tanhap(float x) {
    float y;
    asm("tanh.approx.f32 %0, %1;" : "=f"(y) : "f"(x));
    return y;
}
__device__ __forceinline__ float fsig(float x) {
    return fmaf(0.5f, tanhap(0.5f * x), 0.5f);
}
__device__ __forceinline__ float cellup(float pi, float pf, float pg, float po,
                                        float &c) {
    c = fsig(pf) * c + fsig(pi) * tanhap(pg);
    return fsig(po) * tanhap(c);
}

// 3-row MAC over 5 h-kquads (10 k-pairs) starting at weight offset `off`
__device__ __forceinline__ void mac3(u64 &aA, u64 &aB, u64 &aC,
                                     const ulonglong2* __restrict__ h,
                                     const u64* __restrict__ WA,
                                     const u64* __restrict__ WB,
                                     const u64* __restrict__ WC, int off)
{
#pragma unroll
    for (int i = 0; i < 5; i++) {
        ulonglong2 v = h[i];
        ffma2(aA, v.x, WA[off + 2*i]); ffma2(aA, v.y, WA[off + 2*i + 1]);
        ffma2(aB, v.x, WB[off + 2*i]); ffma2(aB, v.y, WB[off + 2*i + 1]);
        ffma2(aC, v.x, WC[off + 2*i]); ffma2(aC, v.y, WC[off + 2*i + 1]);
    }
}

__global__ void __launch_bounds__(NW * 32, 2)
lstm3_rows(const float* __restrict__ x,
           const float* __restrict__ wih0, const float* __restrict__ whh0,
           const float* __restrict__ bih0, const float* __restrict__ bhh0,
           const float* __restrict__ wih1, const float* __restrict__ whh1,
           const float* __restrict__ bih1, const float* __restrict__ bhh1,
           const float* __restrict__ wih2, const float* __restrict__ whh2,
           const float* __restrict__ bih2, const float* __restrict__ bhh2,
           const float* __restrict__ fcw,  const float* __restrict__ fcb,
           float* __restrict__ out)
{
    // h buffers: [layer][pipe][parity][gb][20 floats]
    __shared__ __align__(16) float4 s_h[3][2][2][GB][5];
    // per-warp, per-gb row-sum scratch, unit-major: ps[gb][u*4+g]
    __shared__ __align__(16) float s_ps[NW][GB][80];

    const int tid  = threadIdx.x;
    const int lane = tid & 31;
    const int wid  = tid >> 5;

    {   // zero h buffers
        float4* p = &s_h[0][0][0][0][0];
        for (int i = tid; i < 3 * 2 * 2 * GB * 5; i += NW * 32)
            p[i] = make_float4(0.f, 0.f, 0.f, 0.f);
    }
    __syncthreads();

    // role map: S0={L1p0,L0p0} S1={L2p0,L0p1} S2={L1p1} S3={L2p1}
    int role, pipe;
    if (wid < 4) { role = 1 + (wid & 1); pipe = wid >> 1; }
    else         { role = 0;             pipe = wid - 4;  }
    const int barid = 1 + pipe;

    const int bbase = blockIdx.x * (2 * GB) + pipe * GB;

    // gate-row assignment (rows: i 0-19, f 20-39, g 40-59, o 60-79)
    const int rA = lane;                 // rows 0..31
    const int rB = lane + 32;            // rows 32..63
    const int rC = 64 + (lane & 15);     // rows 64..79 (lanes 16..31 shadow)
    const int jc = (lane < HID) ? lane : (HID - 1);

    const int adA = (rA % 20) * 4 + rA / 20;
    const int adB = (rB % 20) * 4 + rB / 20;
    const int adC = (rC % 20) * 4 + rC / 20;

    // ---- per-lane register weights ----
    u64 WA[20], WB[20], WC[20];
    float4 Bini, wx4 = make_float4(0.f, 0.f, 0.f, 0.f);
    {
        const float* wi = (role == 0) ? wih0 : ((role == 1) ? wih1 : wih2);
        const float* wh = (role == 0) ? whh0 : ((role == 1) ? whh1 : whh2);
        const float* bi = (role == 0) ? bih0 : ((role == 1) ? bih1 : bih2);
        const float* bh = (role == 0) ? bhh0 : ((role == 1) ? bhh1 : bhh2);
        if (role == 0) {
#pragma unroll
            for (int m = 0; m < 10; m++) {
                WA[m] = *(const u64*)(wh + rA * HID + 2 * m);
                WB[m] = *(const u64*)(wh + rB * HID + 2 * m);
                WC[m] = *(const u64*)(wh + rC * HID + 2 * m);
            }
            wx4 = make_float4(wi[jc], wi[20 + jc], wi[40 + jc], wi[60 + jc]);
        } else {
#pragma unroll
            for (int m = 0; m < 10; m++) {
                WA[m]      = *(const u64*)(wi + rA * HID + 2 * m);
                WA[10 + m] = *(const u64*)(wh + rA * HID + 2 * m);
                WB[m]      = *(const u64*)(wi + rB * HID + 2 * m);
                WB[10 + m] = *(const u64*)(wh + rB * HID + 2 * m);
                WC[m]      = *(const u64*)(wi + rC * HID + 2 * m);
                WC[10 + m] = *(const u64*)(wh + rC * HID + 2 * m);
            }
        }
        Bini = make_float4(bi[jc]      + bh[jc],      bi[20 + jc] + bh[20 + jc],
                           bi[40 + jc] + bh[40 + jc], bi[60 + jc] + bh[60 + jc]);
    }

    float cst[GB] = {0.f, 0.f};
    float xs[GB]  = {0.f, 0.f};

    // pipeline: step n -> L0 computes t=n, L1 t=n-1, L2 t=n-2
    for (int n = 0; n <= T_LEN + 1; n++) {
        if (role == 0) {
            if (n < T_LEN) {
                if ((n & 31) == 0) {
#pragma unroll
                    for (int gb = 0; gb < GB; gb++)
                        xs[gb] = x[(long)(bbase + gb) * T_LEN + n + lane];
                }
                const int pw = n & 1, pr = pw ^ 1;
#pragma unroll
                for (int gb = 0; gb < GB; gb++) {
                    float xv = __shfl_sync(FULLM, xs[gb], n & 31);
                    u64 aA = 0, aB = 0, aC = 0;
                    mac3(aA, aB, aC,
                         (const ulonglong2*)&s_h[0][pipe][pr][gb][0],
                         WA, WB, WC, 0);
                    s_ps[wid][gb][adA] = hadd(aA);
                    s_ps[wid][gb][adB] = hadd(aB);
                    if (lane < 16) s_ps[wid][gb][adC] = hadd(aC);
                    __syncwarp();
                    float4 G = *(const float4*)&s_ps[wid][gb][jc * 4];
                    float gi = fmaf(xv, wx4.x, G.x + Bini.x);
                    float gf = fmaf(xv, wx4.y, G.y + Bini.y);
                    float gg = fmaf(xv, wx4.z, G.z + Bini.z);
                    float go = fmaf(xv, wx4.w, G.w + Bini.w);
                    float hn = cellup(gi, gf, gg, go, cst[gb]);
                    if (lane < HID)
                        ((float*)&s_h[0][pipe][pw][gb][0])[lane] = hn;
                    __syncwarp();
                }
            }
        } else if (role == 1) {
            if (n >= 1 && n <= T_LEN) {
                const int t = n - 1, pw = t & 1, pr = pw ^ 1;
#pragma unroll
                for (int gb = 0; gb < GB; gb++) {
                    u64 aA = 0, aB = 0, aC = 0;
                    mac3(aA, aB, aC,
                         (const ulonglong2*)&s_h[0][pipe][pw][gb][0],
                         WA, WB, WC, 0);                       // h0[t]
                    mac3(aA, aB, aC,
                         (const ulonglong2*)&s_h[1][pipe][pr][gb][0],
                         WA, WB, WC, 10);                      // h1[t-1]
                    s_ps[wid][gb][adA] = hadd(aA);
                    s_ps[wid][gb][adB] = hadd(aB);
                    if (lane < 16) s_ps[wid][gb][adC] = hadd(aC);
                    __syncwarp();
                    float4 G = *(const float4*)&s_ps[wid][gb][jc * 4];
                    float hn = cellup(G.x + Bini.x, G.y + Bini.y,
                                      G.z + Bini.z, G.w + Bini.w, cst[gb]);
                    if (lane < HID)
                        ((float*)&s_h[1][pipe][pw][gb][0])[lane] = hn;
                    __syncwarp();
                }
            }
        } else {
            if (n >= 2) {
                const int t = n - 2, pw = t & 1, pr = pw ^ 1;
#pragma unroll
                for (int gb = 0; gb < GB; gb++) {
                    u64 aA = 0, aB = 0, aC = 0;
                    mac3(aA, aB, aC,
                         (const ulonglong2*)&s_h[1][pipe][pw][gb][0],
                         WA, WB, WC, 0);                       // h1[t]
                    mac3(aA, aB, aC,
                         (const ulonglong2*)&s_h[2][pipe][pr][gb][0],
                         WA, WB, WC, 10);                      // h2[t-1]
                    s_ps[wid][gb][adA] = hadd(aA);
                    s_ps[wid][gb][adB] = hadd(aB);
                    if (lane < 16) s_ps[wid][gb][adC] = hadd(aC);
                    __syncwarp();
                    float4 G = *(const float4*)&s_ps[wid][gb][jc * 4];
                    float hn = cellup(G.x + Bini.x, G.y + Bini.y,
                                      G.z + Bini.z, G.w + Bini.w, cst[gb]);
                    if (lane < HID)
                        ((float*)&s_h[2][pipe][pw][gb][0])[lane] = hn;
                    __syncwarp();
                }
            }
        }
        // per-pipe barrier: couples only this pipe's 3 warps (4 domains/SM)
        asm volatile("bar.sync %0, 96;" :: "r"(barid) : "memory");
    }

    // ---- final FC on h2[T-1] by the L2 warps ----
    if (role == 2) {
        const int pfin = (T_LEN - 1) & 1;
#pragma unroll
        for (int gb = 0; gb < GB; gb++) {
            const int b = bbase + gb;
            float hv = ((const float*)&s_h[2][pipe][pfin][gb][0])[jc];
            float p0 = (lane < HID) ? hv * fcw[jc]       : 0.f;
            float p1 = (lane < HID) ? hv * fcw[HID + jc] : 0.f;
#pragma unroll
            for (int off = 16; off > 0; off >>= 1) {
                p0 += __shfl_xor_sync(FULLM, p0, off);
                p1 += __shfl_xor_sync(FULLM, p1, off);
            }
            if (lane == 0) {
                out[b * 2 + 0] = p0 + fcb[0];
                out[b * 2 + 1] = p1 + fcb[1];
            }
        }
    }
}

extern "C" void kernel_launch(void* const* d_in, const int* in_sizes, int n_in,
                              void* d_out, int out_size) {
    const float* x    = (const float*)d_in[0];
    const float* wih0 = (const float*)d_in[1];
    const float* whh0 = (const float*)d_in[2];
    const float* bih0 = (const float*)d_in[3];
    const float* bhh0 = (const float*)d_in[4];
    const float* wih1 = (const float*)d_in[5];
    const float* whh1 = (const float*)d_in[6];
    const float* bih1 = (const float*)d_in[7];
    const float* bhh1 = (const float*)d_in[8];
    const float* wih2 = (const float*)d_in[9];
    const float* whh2 = (const float*)d_in[10];
    const float* bih2 = (const float*)d_in[11];
    const float* bhh2 = (const float*)d_in[12];
    const float* fcw  = (const float*)d_in[13];
    const float* fcb  = (const float*)d_in[14];
    float* out = (float*)d_out;

    // 256 blocks x 4 batches (2 pipes x GB=2); 2 blocks co-resident per SM
    lstm3_rows<<<256, NW * 32>>>(x, wih0, whh0, bih0, bhh0,
                                 wih1, whh1, bih1, bhh1,
                                 wih2, whh2, bih2, bhh2,
                                 fcw, fcb, out);
}

// round 15
// speedup vs baseline: 1.7083x; 1.0365x over previous
#include <cuda_runtime.h>
#include <cuda_bf16.h>

// 3-layer LSTM, B=1024, T=1024, H=20, IN=1, OUT=2, FC on last h2.
// R15 = R14 (layer pipeline, gate-row split, register weights, tanh.approx,
// 2 blocks/SM, per-pipe named barriers) + TWO timesteps per barrier interval:
// L0 does t={2m,2m+1}, L1 t={2m-2,2m-1}, L2 t={2m-4,2m-3}; h buffers 4-deep
// (slot = t&3). Named barrier count halves: 1026 -> 514.

#define T_LEN 1024
#define HID   20
#define FULLM 0xffffffffu
#define NW    6
#define GB    2

typedef unsigned long long u64;

__device__ __forceinline__ void ffma2(u64 &acc, u64 a, u64 b) {
    asm("fma.rn.f32x2 %0, %1, %2, %0;" : "+l"(acc) : "l"(a), "l"(b));
}
__device__ __forceinline__ float hadd(u64 v) {
    float lo, hi;
    asm("mov.b64 {%0, %1}, %2;" : "=f"(lo), "=f"(hi) : "l"(v));
    return lo + hi;
}

// ---- MUFU.TANH-based activations ----
__device__ __forceinline__ float tanhap(float x) {
    float y;
    asm("tanh.approx.f32 %0, %1;" : "=f"(y) : "f"(x));
    return y;
}
__device__ __forceinline__ float fsig(float x) {
    return fmaf(0.5f, tanhap(0.5f * x), 0.5f);
}
__device__ __forceinline__ float cellup(float pi, float pf, float pg, float po,
                                        float &c) {
    c = fsig(pf) * c + fsig(pi) * tanhap(pg);
    return fsig(po) * tanhap(c);
}

// 3-row MAC over 5 h-kquads (10 k-pairs) starting at weight offset `off`
__device__ __forceinline__ void mac3(u64 &aA, u64 &aB, u64 &aC,
                                     const ulonglong2* __restrict__ h,
                                     const u64* __restrict__ WA,
                                     const u64* __restrict__ WB,
                                     const u64* __restrict__ WC, int off)
{
#pragma unroll
    for (int i = 0; i < 5; i++) {
        ulonglong2 v = h[i];
        ffma2(aA, v.x, WA[off + 2*i]); ffma2(aA, v.y, WA[off + 2*i + 1]);
        ffma2(aB, v.x, WB[off + 2*i]); ffma2(aB, v.y, WB[off + 2*i + 1]);
        ffma2(aC, v.x, WC[off + 2*i]); ffma2(aC, v.y, WC[off + 2*i + 1]);
    }
}

__global__ void __launch_bounds__(NW * 32, 2)
lstm3_rows(const float* __restrict__ x,
           const float* __restrict__ wih0, const float* __restrict__ whh0,
           const float* __restrict__ bih0, const float* __restrict__ bhh0,
           const float* __restrict__ wih1, const float* __restrict__ whh1,
           const float* __restrict__ bih1, const float* __restrict__ bhh1,
           const float* __restrict__ wih2, const float* __restrict__ whh2,
           const float* __restrict__ bih2, const float* __restrict__ bhh2,
           const float* __restrict__ fcw,  const float* __restrict__ fcb,
           float* __restrict__ out)
{
    // h buffers: [layer][pipe][slot = t&3][gb][20 floats]
    __shared__ __align__(16) float4 s_h[3][2][4][GB][5];
    // per-warp, per-gb row-sum scratch, unit-major: ps[gb][u*4+g]
    __shared__ __align__(16) float s_ps[NW][GB][80];

    const int tid  = threadIdx.x;
    const int lane = tid & 31;
    const int wid  = tid >> 5;

    {   // zero all 4 slots of all h buffers
        float4* p = &s_h[0][0][0][0][0];
        for (int i = tid; i < 3 * 2 * 4 * GB * 5; i += NW * 32)
            p[i] = make_float4(0.f, 0.f, 0.f, 0.f);
    }
    __syncthreads();

    // role map: S0={L1p0,L0p0} S1={L2p0,L0p1} S2={L1p1} S3={L2p1}
    int role, pipe;
    if (wid < 4) { role = 1 + (wid & 1); pipe = wid >> 1; }
    else         { role = 0;             pipe = wid - 4;  }
    const int barid = 1 + pipe;

    const int bbase = blockIdx.x * (2 * GB) + pipe * GB;

    // gate-row assignment (rows: i 0-19, f 20-39, g 40-59, o 60-79)
    const int rA = lane;                 // rows 0..31
    const int rB = lane + 32;            // rows 32..63
    const int rC = 64 + (lane & 15);     // rows 64..79 (lanes 16..31 shadow)
    const int jc = (lane < HID) ? lane : (HID - 1);

    const int adA = (rA % 20) * 4 + rA / 20;
    const int adB = (rB % 20) * 4 + rB / 20;
    const int adC = (rC % 20) * 4 + rC / 20;

    // ---- per-lane register weights ----
    u64 WA[20], WB[20], WC[20];
    float4 Bini, wx4 = make_float4(0.f, 0.f, 0.f, 0.f);
    {
        const float* wi = (role == 0) ? wih0 : ((role == 1) ? wih1 : wih2);
        const float* wh = (role == 0) ? whh0 : ((role == 1) ? whh1 : whh2);
        const float* bi = (role == 0) ? bih0 : ((role == 1) ? bih1 : bih2);
        const float* bh = (role == 0) ? bhh0 : ((role == 1) ? bhh1 : bhh2);
        if (role == 0) {
#pragma unroll
            for (int m = 0; m < 10; m++) {
                WA[m] = *(const u64*)(wh + rA * HID + 2 * m);
                WB[m] = *(const u64*)(wh + rB * HID + 2 * m);
                WC[m] = *(const u64*)(wh + rC * HID + 2 * m);
            }
            wx4 = make_float4(wi[jc], wi[20 + jc], wi[40 + jc], wi[60 + jc]);
        } else {
#pragma unroll
            for (int m = 0; m < 10; m++) {
                WA[m]      = *(const u64*)(wi + rA * HID + 2 * m);
                WA[10 + m] = *(const u64*)(wh + rA * HID + 2 * m);
                WB[m]      = *(const u64*)(wi + rB * HID + 2 * m);
                WB[10 + m] = *(const u64*)(wh + rB * HID + 2 * m);
                WC[m]      = *(const u64*)(wi + rC * HID + 2 * m);
                WC[10 + m] = *(const u64*)(wh + rC * HID + 2 * m);
            }
        }
        Bini = make_float4(bi[jc]      + bh[jc],      bi[20 + jc] + bh[20 + jc],
                           bi[40 + jc] + bh[40 + jc], bi[60 + jc] + bh[60 + jc]);
    }

    float cst[GB] = {0.f, 0.f};
    float xs[GB]  = {0.f, 0.f};

    // interval m: L0 does t=2m,2m+1; L1 t=2m-2,2m-1; L2 t=2m-4,2m-3
    for (int m = 0; m <= 513; m++) {
        if (role == 0) {
            if (m <= 511) {
#pragma unroll
                for (int s = 0; s < 2; s++) {
                    const int t = 2 * m + s;
                    if ((t & 31) == 0) {
#pragma unroll
                        for (int gb = 0; gb < GB; gb++)
                            xs[gb] = x[(long)(bbase + gb) * T_LEN + t + lane];
                    }
                    const int pw = t & 3, pr = (t - 1) & 3;
#pragma unroll
                    for (int gb = 0; gb < GB; gb++) {
                        float xv = __shfl_sync(FULLM, xs[gb], t & 31);
                        u64 aA = 0, aB = 0, aC = 0;
                        mac3(aA, aB, aC,
                             (const ulonglong2*)&s_h[0][pipe][pr][gb][0],
                             WA, WB, WC, 0);
                        s_ps[wid][gb][adA] = hadd(aA);
                        s_ps[wid][gb][adB] = hadd(aB);
                        if (lane < 16) s_ps[wid][gb][adC] = hadd(aC);
                        __syncwarp();
                        float4 G = *(const float4*)&s_ps[wid][gb][jc * 4];
                        float gi = fmaf(xv, wx4.x, G.x + Bini.x);
                        float gf = fmaf(xv, wx4.y, G.y + Bini.y);
                        float gg = fmaf(xv, wx4.z, G.z + Bini.z);
                        float go = fmaf(xv, wx4.w, G.w + Bini.w);
                        float hn = cellup(gi, gf, gg, go, cst[gb]);
                        if (lane < HID)
                            ((float*)&s_h[0][pipe][pw][gb][0])[lane] = hn;
                        __syncwarp();
                    }
                }
            }
        } else if (role == 1) {
            if (m >= 1 && m <= 512) {
#pragma unroll
                for (int s = 0; s < 2; s++) {
                    const int t = 2 * m - 2 + s;
                    const int pw = t & 3, pr = (t - 1) & 3;
#pragma unroll
                    for (int gb = 0; gb < GB; gb++) {
                        u64 aA = 0, aB = 0, aC = 0;
                        mac3(aA, aB, aC,
                             (const ulonglong2*)&s_h[0][pipe][pw][gb][0],
                             WA, WB, WC, 0);                       // h0[t]
                        mac3(aA, aB, aC,
                             (const ulonglong2*)&s_h[1][pipe][pr][gb][0],
                             WA, WB, WC, 10);                      // h1[t-1]
                        s_ps[wid][gb][adA] = hadd(aA);
                        s_ps[wid][gb][adB] = hadd(aB);
                        if (lane < 16) s_ps[wid][gb][adC] = hadd(aC);
                        __syncwarp();
                        float4 G = *(const float4*)&s_ps[wid][gb][jc * 4];
                        float hn = cellup(G.x + Bini.x, G.y + Bini.y,
                                          G.z + Bini.z, G.w + Bini.w, cst[gb]);
                        if (lane < HID)
                            ((float*)&s_h[1][pipe][pw][gb][0])[lane] = hn;
                        __syncwarp();
                    }
                }
            }
        } else {
            if (m >= 2) {
#pragma unroll
                for (int s = 0; s < 2; s++) {
                    const int t = 2 * m - 4 + s;
                    const int pw = t & 3, pr = (t - 1) & 3;
#pragma unroll
                    for (int gb = 0; gb < GB; gb++) {
                        u64 aA = 0, aB = 0, aC = 0;
                        mac3(aA, aB, aC,
                             (const ulonglong2*)&s_h[1][pipe][pw][gb][0],
                             WA, WB, WC, 0);                       // h1[t]
                        mac3(aA, aB, aC,
                             (const ulonglong2*)&s_h[2][pipe][pr][gb][0],
                             WA, WB, WC, 10);                      // h2[t-1]
                        s_ps[wid][gb][adA] = hadd(aA);
                        s_ps[wid][gb][adB] = hadd(aB);
                        if (lane < 16) s_ps[wid][gb][adC] = hadd(aC);
                        __syncwarp();
                        float4 G = *(const float4*)&s_ps[wid][gb][jc * 4];
                        float hn = cellup(G.x + Bini.x, G.y + Bini.y,
                                          G.z + Bini.z, G.w + Bini.w, cst[gb]);
                        if (lane < HID)
                            ((float*)&s_h[2][pipe][pw][gb][0])[lane] = hn;
                        __syncwarp();
                    }
                }
            }
        }
        // per-pipe barrier once per 2 timesteps
        asm volatile("bar.sync %0, 96;" :: "r"(barid) : "memory");
    }

    // ---- final FC on h2[T-1] (t=1023, slot 3) by the L2 warps ----
    if (role == 2) {
#pragma unroll
        for (int gb = 0; gb < GB; gb++) {
            const int b = bbase + gb;
            float hv = ((const float*)&s_h[2][pipe][3][gb][0])[jc];
            float p0 = (lane < HID) ? hv * fcw[jc]       : 0.f;
            float p1 = (lane < HID) ? hv * fcw[HID + jc] : 0.f;
#pragma unroll
            for (int off = 16; off > 0; off >>= 1) {
                p0 += __shfl_xor_sync(FULLM, p0, off);
                p1 += __shfl_xor_sync(FULLM, p1, off);
            }
            if (lane == 0) {
                out[b * 2 + 0] = p0 + fcb[0];
                out[b * 2 + 1] = p1 + fcb[1];
            }
        }
    }
}

extern "C" void kernel_launch(void* const* d_in, const int* in_sizes, int n_in,
                              void* d_out, int out_size) {
    const float* x    = (const float*)d_in[0];
    const float* wih0 = (const float*)d_in[1];
    const float* whh0 = (const float*)d_in[2];
    const float* bih0 = (const float*)d_in[3];
    const float* bhh0 = (const float*)d_in[4];
    const float* wih1 = (const float*)d_in[5];
    const float* whh1 = (const float*)d_in[6];
    const float* bih1 = (const float*)d_in[7];
    const float* bhh1 = (const float*)d_in[8];
    const float* wih2 = (const float*)d_in[9];
    const float* whh2 = (const float*)d_in[10];
    const float* bih2 = (const float*)d_in[11];
    const float* bhh2 = (const float*)d_in[12];
    const float* fcw  = (const float*)d_in[13];
    const float* fcb  = (const float*)d_in[14];
    float* out = (float*)d_out;

    // 256 blocks x 4 batches (2 pipes x GB=2); 2 blocks co-resident per SM
    lstm3_rows<<<256, NW * 32>>>(x, wih0, whh0, bih0, bhh0,
                                 wih1, whh1, bih1, bhh1,
                                 wih2, whh2, bih2, bhh2,
                                 fcw, fcb, out);
}

// round 16
// speedup vs baseline: 1.7446x; 1.0212x over previous
#include <cuda_runtime.h>
#include <cuda_bf16.h>

// 3-layer LSTM, B=1024, T=1024, H=20, IN=1, OUT=2, FC on last h2.
// R16 = R15 (layer pipeline, gate-row split, register weights, tanh.approx,
// 2 blocks/SM, per-pipe named barriers, 2 steps/barrier) + batch interleave:
// each step is phase A (both gb MACs -> scratch) / one syncwarp /
// phase B (both gb cell updates -> h). Syncwarps per step: 4 -> 2, and gb1's
// MAC issue overlaps gb0's LDS+activation latency tail.

#define T_LEN 1024
#define HID   20
#define FULLM 0xffffffffu
#define NW    6
#define GB    2

typedef unsigned long long u64;

__device__ __forceinline__ void ffma2(u64 &acc, u64 a, u64 b) {
    asm("fma.rn.f32x2 %0, %1, %2, %0;" : "+l"(acc) : "l"(a), "l"(b));
}
__device__ __forceinline__ float hadd(u64 v) {
    float lo, hi;
    asm("mov.b64 {%0, %1}, %2;" : "=f"(lo), "=f"(hi) : "l"(v));
    return lo + hi;
}

// ---- MUFU.TANH-based activations ----
__device__ __forceinline__ float tanhap(float x) {
    float y;
    asm("tanh.approx.f32 %0, %1;" : "=f"(y) : "f"(x));
    return y;
}
__device__ __forceinline__ float fsig(float x) {
    return fmaf(0.5f, tanhap(0.5f * x), 0.5f);
}
__device__ __forceinline__ float cellup(float pi, float pf, float pg, float po,
                                        float &c) {
    c = fsig(pf) * c + fsig(pi) * tanhap(pg);
    return fsig(po) * tanhap(c);
}

// 3-row MAC over 5 h-kquads (10 k-pairs) starting at weight offset `off`
__device__ __forceinline__ void mac3(u64 &aA, u64 &aB, u64 &aC,
                                     const ulonglong2* __restrict__ h,
                                     const u64* __restrict__ WA,
                                     const u64* __restrict__ WB,
                                     const u64* __restrict__ WC, int off)
{
#pragma unroll
    for (int i = 0; i < 5; i++) {
        ulonglong2 v = h[i];
        ffma2(aA, v.x, WA[off + 2*i]); ffma2(aA, v.y, WA[off + 2*i + 1]);
        ffma2(aB, v.x, WB[off + 2*i]); ffma2(aB, v.y, WB[off + 2*i + 1]);
        ffma2(aC, v.x, WC[off + 2*i]); ffma2(aC, v.y, WC[off + 2*i + 1]);
    }
}

__global__ void __launch_bounds__(NW * 32, 2)
lstm3_rows(const float* __restrict__ x,
           const float* __restrict__ wih0, const float* __restrict__ whh0,
           const float* __restrict__ bih0, const float* __restrict__ bhh0,
           const float* __restrict__ wih1, const float* __restrict__ whh1,
           const float* __restrict__ bih1, const float* __restrict__ bhh1,
           const float* __restrict__ wih2, const float* __restrict__ whh2,
           const float* __restrict__ bih2, const float* __restrict__ bhh2,
           const float* __restrict__ fcw,  const float* __restrict__ fcb,
           float* __restrict__ out)
{
    // h buffers: [layer][pipe][slot = t&3][gb][20 floats]
    __shared__ __align__(16) float4 s_h[3][2][4][GB][5];
    // per-warp, per-gb row-sum scratch, unit-major: ps[gb][u*4+g]
    __shared__ __align__(16) float s_ps[NW][GB][80];

    const int tid  = threadIdx.x;
    const int lane = tid & 31;
    const int wid  = tid >> 5;

    {   // zero all 4 slots of all h buffers
        float4* p = &s_h[0][0][0][0][0];
        for (int i = tid; i < 3 * 2 * 4 * GB * 5; i += NW * 32)
            p[i] = make_float4(0.f, 0.f, 0.f, 0.f);
    }
    __syncthreads();

    // role map: S0={L1p0,L0p0} S1={L2p0,L0p1} S2={L1p1} S3={L2p1}
    int role, pipe;
    if (wid < 4) { role = 1 + (wid & 1); pipe = wid >> 1; }
    else         { role = 0;             pipe = wid - 4;  }
    const int barid = 1 + pipe;

    const int bbase = blockIdx.x * (2 * GB) + pipe * GB;

    // gate-row assignment (rows: i 0-19, f 20-39, g 40-59, o 60-79)
    const int rA = lane;                 // rows 0..31
    const int rB = lane + 32;            // rows 32..63
    const int rC = 64 + (lane & 15);     // rows 64..79 (lanes 16..31 shadow)
    const int jc = (lane < HID) ? lane : (HID - 1);

    const int adA = (rA % 20) * 4 + rA / 20;
    const int adB = (rB % 20) * 4 + rB / 20;
    const int adC = (rC % 20) * 4 + rC / 20;

    // ---- per-lane register weights ----
    u64 WA[20], WB[20], WC[20];
    float4 Bini, wx4 = make_float4(0.f, 0.f, 0.f, 0.f);
    {
        const float* wi = (role == 0) ? wih0 : ((role == 1) ? wih1 : wih2);
        const float* wh = (role == 0) ? whh0 : ((role == 1) ? whh1 : whh2);
        const float* bi = (role == 0) ? bih0 : ((role == 1) ? bih1 : bih2);
        const float* bh = (role == 0) ? bhh0 : ((role == 1) ? bhh1 : bhh2);
        if (role == 0) {
#pragma unroll
            for (int m = 0; m < 10; m++) {
                WA[m] = *(const u64*)(wh + rA * HID + 2 * m);
                WB[m] = *(const u64*)(wh + rB * HID + 2 * m);
                WC[m] = *(const u64*)(wh + rC * HID + 2 * m);
            }
            wx4 = make_float4(wi[jc], wi[20 + jc], wi[40 + jc], wi[60 + jc]);
        } else {
#pragma unroll
            for (int m = 0; m < 10; m++) {
                WA[m]      = *(const u64*)(wi + rA * HID + 2 * m);
                WA[10 + m] = *(const u64*)(wh + rA * HID + 2 * m);
                WB[m]      = *(const u64*)(wi + rB * HID + 2 * m);
                WB[10 + m] = *(const u64*)(wh + rB * HID + 2 * m);
                WC[m]      = *(const u64*)(wi + rC * HID + 2 * m);
                WC[10 + m] = *(const u64*)(wh + rC * HID + 2 * m);
            }
        }
        Bini = make_float4(bi[jc]      + bh[jc],      bi[20 + jc] + bh[20 + jc],
                           bi[40 + jc] + bh[40 + jc], bi[60 + jc] + bh[60 + jc]);
    }

    float cst[GB] = {0.f, 0.f};
    float xs[GB]  = {0.f, 0.f};

    // interval m: L0 does t=2m,2m+1; L1 t=2m-2,2m-1; L2 t=2m-4,2m-3
    for (int m = 0; m <= 513; m++) {
        if (role == 0) {
            if (m <= 511) {
#pragma unroll
                for (int s = 0; s < 2; s++) {
                    const int t = 2 * m + s;
                    if ((t & 31) == 0) {
#pragma unroll
                        for (int gb = 0; gb < GB; gb++)
                            xs[gb] = x[(long)(bbase + gb) * T_LEN + t + lane];
                    }
                    const int pw = t & 3, pr = (t - 1) & 3;
                    // phase A: both gb MACs
                    float xv0 = __shfl_sync(FULLM, xs[0], t & 31);
                    float xv1 = __shfl_sync(FULLM, xs[1], t & 31);
                    u64 aA0 = 0, aB0 = 0, aC0 = 0;
                    u64 aA1 = 0, aB1 = 0, aC1 = 0;
                    mac3(aA0, aB0, aC0,
                         (const ulonglong2*)&s_h[0][pipe][pr][0][0],
                         WA, WB, WC, 0);
                    mac3(aA1, aB1, aC1,
                         (const ulonglong2*)&s_h[0][pipe][pr][1][0],
                         WA, WB, WC, 0);
                    s_ps[wid][0][adA] = hadd(aA0);
                    s_ps[wid][0][adB] = hadd(aB0);
                    if (lane < 16) s_ps[wid][0][adC] = hadd(aC0);
                    s_ps[wid][1][adA] = hadd(aA1);
                    s_ps[wid][1][adB] = hadd(aB1);
                    if (lane < 16) s_ps[wid][1][adC] = hadd(aC1);
                    __syncwarp();
                    // phase B: both gb cell updates
                    float4 G0 = *(const float4*)&s_ps[wid][0][jc * 4];
                    float4 G1 = *(const float4*)&s_ps[wid][1][jc * 4];
                    float h0 = cellup(fmaf(xv0, wx4.x, G0.x + Bini.x),
                                      fmaf(xv0, wx4.y, G0.y + Bini.y),
                                      fmaf(xv0, wx4.z, G0.z + Bini.z),
                                      fmaf(xv0, wx4.w, G0.w + Bini.w), cst[0]);
                    float h1 = cellup(fmaf(xv1, wx4.x, G1.x + Bini.x),
                                      fmaf(xv1, wx4.y, G1.y + Bini.y),
                                      fmaf(xv1, wx4.z, G1.z + Bini.z),
                                      fmaf(xv1, wx4.w, G1.w + Bini.w), cst[1]);
                    if (lane < HID) {
                        ((float*)&s_h[0][pipe][pw][0][0])[lane] = h0;
                        ((float*)&s_h[0][pipe][pw][1][0])[lane] = h1;
                    }
                    __syncwarp();
                }
            }
        } else if (role == 1) {
            if (m >= 1 && m <= 512) {
#pragma unroll
                for (int s = 0; s < 2; s++) {
                    const int t = 2 * m - 2 + s;
                    const int pw = t & 3, pr = (t - 1) & 3;
                    u64 aA0 = 0, aB0 = 0, aC0 = 0;
                    u64 aA1 = 0, aB1 = 0, aC1 = 0;
                    mac3(aA0, aB0, aC0,
                         (const ulonglong2*)&s_h[0][pipe][pw][0][0],
                         WA, WB, WC, 0);                       // h0[t]
                    mac3(aA0, aB0, aC0,
                         (const ulonglong2*)&s_h[1][pipe][pr][0][0],
                         WA, WB, WC, 10);                      // h1[t-1]
                    mac3(aA1, aB1, aC1,
                         (const ulonglong2*)&s_h[0][pipe][pw][1][0],
                         WA, WB, WC, 0);
                    mac3(aA1, aB1, aC1,
                         (const ulonglong2*)&s_h[1][pipe][pr][1][0],
                         WA, WB, WC, 10);
                    s_ps[wid][0][adA] = hadd(aA0);
                    s_ps[wid][0][adB] = hadd(aB0);
                    if (lane < 16) s_ps[wid][0][adC] = hadd(aC0);
                    s_ps[wid][1][adA] = hadd(aA1);
                    s_ps[wid][1][adB] = hadd(aB1);
                    if (lane < 16) s_ps[wid][1][adC] = hadd(aC1);
                    __syncwarp();
                    float4 G0 = *(const float4*)&s_ps[wid][0][jc * 4];
                    float4 G1 = *(const float4*)&s_ps[wid][1][jc * 4];
                    float h0 = cellup(G0.x + Bini.x, G0.y + Bini.y,
                                      G0.z + Bini.z, G0.w + Bini.w, cst[0]);
                    float h1 = cellup(G1.x + Bini.x, G1.y + Bini.y,
                                      G1.z + Bini.z, G1.w + Bini.w, cst[1]);
                    if (lane < HID) {
                        ((float*)&s_h[1][pipe][pw][0][0])[lane] = h0;
                        ((float*)&s_h[1][pipe][pw][1][0])[lane] = h1;
                    }
                    __syncwarp();
                }
            }
        } else {
            if (m >= 2) {
#pragma unroll
                for (int s = 0; s < 2; s++) {
                    const int t = 2 * m - 4 + s;
                    const int pw = t & 3, pr = (t - 1) & 3;
                    u64 aA0 = 0, aB0 = 0, aC0 = 0;
                    u64 aA1 = 0, aB1 = 0, aC1 = 0;
                    mac3(aA0, aB0, aC0,
                         (const ulonglong2*)&s_h[1][pipe][pw][0][0],
                         WA, WB, WC, 0);                       // h1[t]
                    mac3(aA0, aB0, aC0,
                         (const ulonglong2*)&s_h[2][pipe][pr][0][0],
                         WA, WB, WC, 10);                      // h2[t-1]
                    mac3(aA1, aB1, aC1,
                         (const ulonglong2*)&s_h[1][pipe][pw][1][0],
                         WA, WB, WC, 0);
                    mac3(aA1, aB1, aC1,
                         (const ulonglong2*)&s_h[2][pipe][pr][1][0],
                         WA, WB, WC, 10);
                    s_ps[wid][0][adA] = hadd(aA0);
                    s_ps[wid][0][adB] = hadd(aB0);
                    if (lane < 16) s_ps[wid][0][adC] = hadd(aC0);
                    s_ps[wid][1][adA] = hadd(aA1);
                    s_ps[wid][1][adB] = hadd(aB1);
                    if (lane < 16) s_ps[wid][1][adC] = hadd(aC1);
                    __syncwarp();
                    float4 G0 = *(const float4*)&s_ps[wid][0][jc * 4];
                    float4 G1 = *(const float4*)&s_ps[wid][1][jc * 4];
                    float h0 = cellup(G0.x + Bini.x, G0.y + Bini.y,
                                      G0.z + Bini.z, G0.w + Bini.w, cst[0]);
                    float h1 = cellup(G1.x + Bini.x, G1.y + Bini.y,
                                      G1.z + Bini.z, G1.w + Bini.w, cst[1]);
                    if (lane < HID) {
                        ((float*)&s_h[2][pipe][pw][0][0])[lane] = h0;
                        ((float*)&s_h[2][pipe][pw][1][0])[lane] = h1;
                    }
                    __syncwarp();
                }
            }
        }
        // per-pipe barrier once per 2 timesteps
        asm volatile("bar.sync %0, 96;" :: "r"(barid) : "memory");
    }

    // ---- final FC on h2[T-1] (t=1023, slot 3) by the L2 warps ----
    if (role == 2) {
#pragma unroll
        for (int gb = 0; gb < GB; gb++) {
            const int b = bbase + gb;
            float hv = ((const float*)&s_h[2][pipe][3][gb][0])[jc];
            float p0 = (lane < HID) ? hv * fcw[jc]       : 0.f;
            float p1 = (lane < HID) ? hv * fcw[HID + jc] : 0.f;
#pragma unroll
            for (int off = 16; off > 0; off >>= 1) {
                p0 += __shfl_xor_sync(FULLM, p0, off);
                p1 += __shfl_xor_sync(FULLM, p1, off);
            }
            if (lane == 0) {
                out[b * 2 + 0] = p0 + fcb[0];
                out[b * 2 + 1] = p1 + fcb[1];
            }
        }
    }
}

extern "C" void kernel_launch(void* const* d_in, const int* in_sizes, int n_in,
                              void* d_out, int out_size) {
    const float* x    = (const float*)d_in[0];
    const float* wih0 = (const float*)d_in[1];
    const float* whh0 = (const float*)d_in[2];
    const float* bih0 = (const float*)d_in[3];
    const float* bhh0 = (const float*)d_in[4];
    const float* wih1 = (const float*)d_in[5];
    const float* whh1 = (const float*)d_in[6];
    const float* bih1 = (const float*)d_in[7];
    const float* bhh1 = (const float*)d_in[8];
    const float* wih2 = (const float*)d_in[9];
    const float* whh2 = (const float*)d_in[10];
    const float* bih2 = (const float*)d_in[11];
    const float* bhh2 = (const float*)d_in[12];
    const float* fcw  = (const float*)d_in[13];
    const float* fcb  = (const float*)d_in[14];
    float* out = (float*)d_out;

    // 256 blocks x 4 batches (2 pipes x GB=2); 2 blocks co-resident per SM
    lstm3_rows<<<256, NW * 32>>>(x, wih0, whh0, bih0, bhh0,
                                 wih1, whh1, bih1, bhh1,
                                 wih2, whh2, bih2, bhh2,
                                 fcw, fcb, out);
}